// round 15
// baseline (speedup 1.0000x reference)
#include <cuda_runtime.h>
#include <cuda_fp16.h>
#include <stdint.h>

#define B_ 16
#define C_ 4
#define L_ 4096
#define K_ 256
#define S_ 128
#define W_ (L_ - S_ + 1)   // 3969
#define EPS_ 1e-8f

#define WT 128             // w per block (MMA M)
#define KT 64              // k per block (MMA N)

// Precomputed in prep, consumed via pure cp.async in main:
//  g_xe[bc][j] = (xh[2j], xh[2j+1])   g_xo[bc][j] = (xh[2j+1], xh[2j+2])
//  padded regions stay zero (device globals zero-init, prep never writes
//  them) -> only consumed by iv=0 rows, so they never affect the max.
__device__ __align__(16) uint32_t g_xe[B_ * C_ * 2176];
__device__ __align__(16) uint32_t g_xo[B_ * C_ * 2176];
__device__ __align__(16) __half  g_invh[B_ * C_ * 4096];   // padded W, fp16
// Shapelets normalized -> fp16, PRE-SWIZZLED per-(ktile,channel) 16KB tile
__device__ __align__(256) half g_shpB[C_ * K_ * S_];   // [4 ktiles][4 c][64*128]

// ---------------------------------------------------------------------------
// Merged prep kernel:
//  blocks [0,1024): inverse norms + even/odd half2 strip arrays (+ zero out)
//  blocks [1024,1536): shapelet normalize -> swizzled fp16 image
// ---------------------------------------------------------------------------
__global__ void k_prep(const float* __restrict__ x, const float* __restrict__ shp,
                       float* __restrict__ out) {
    int tid = threadIdx.x;
    if (blockIdx.x < 1024) {
        __shared__ float xs[384];
        int bc = blockIdx.x >> 4;
        int w0 = (blockIdx.x & 15) * 256;
        if (blockIdx.x < 16) out[blockIdx.x * 256 + tid] = 0.f;
        for (int i = tid; i < 383; i += 256) {
            int g = w0 + i;
            xs[i] = (g < L_) ? x[bc * L_ + g] : 0.f;
        }
        __syncthreads();
        int w = w0 + tid;
        if (w < W_) {
            float sum = 0.f;
#pragma unroll 8
            for (int s = 0; s < S_; s++) { float t = xs[tid + s]; sum += t * t; }
            g_invh[bc * 4096 + w] = __float2half(1.f / fmaxf(sqrtf(sum), EPS_));
        }
        if (tid < 128) {
            int j = (w0 >> 1) + tid;
            half2 e = __floats2half2_rn(xs[2 * tid],     xs[2 * tid + 1]);
            half2 o = __floats2half2_rn(xs[2 * tid + 1], xs[2 * tid + 2]);
            g_xe[bc * 2176 + j] = *(uint32_t*)&e;
            g_xo[bc * 2176 + j] = *(uint32_t*)&o;
        }
    } else {
        __shared__ float wsum[8];
        int idx = blockIdx.x - 1024;              // 0..511
        int p = idx * 2 + (tid >> 7);             // (c,k) pair id, 0..1023
        int c = p >> 8, k = p & 255;
        int s = tid & 127;
        float v = shp[(c * K_ + k) * S_ + s];
        float sq = v * v;
#pragma unroll
        for (int o = 16; o > 0; o >>= 1) sq += __shfl_xor_sync(0xffffffffu, sq, o);
        if ((tid & 31) == 0) wsum[tid >> 5] = sq;
        __syncthreads();
        int g4 = (tid >> 7) * 4;
        float tot = wsum[g4] + wsum[g4 + 1] + wsum[g4 + 2] + wsum[g4 + 3];
        float inv = 1.f / fmaxf(sqrtf(tot), EPS_);
        int tile = (k >> 6) * C_ + c;             // 4 ktiles of 64 rows
        int row = k & 63;
        uint32_t off = (uint32_t)row * 256u
                     + ((((uint32_t)(s >> 3)) ^ (row & 7)) << 4)
                     + (uint32_t)(s & 7) * 2u;
        *(half*)((char*)g_shpB + (size_t)tile * 16384 + off) = __float2half(v * inv);
    }
}

// ---------------------------------------------------------------------------
__device__ __forceinline__ void ldsm4(uint32_t (&r)[4], uint32_t addr) {
    asm volatile("ldmatrix.sync.aligned.m8n8.x4.shared.b16 {%0,%1,%2,%3}, [%4];"
                 : "=r"(r[0]), "=r"(r[1]), "=r"(r[2]), "=r"(r[3]) : "r"(addr));
}
__device__ __forceinline__ void mma16816(float (&d)[4], const uint32_t (&a)[4],
                                         uint32_t b0, uint32_t b1) {
    asm volatile("mma.sync.aligned.m16n8k16.row.col.f32.f16.f16.f32 "
                 "{%0,%1,%2,%3}, {%4,%5,%6,%7}, {%8,%9}, {%0,%1,%2,%3};"
                 : "+f"(d[0]), "+f"(d[1]), "+f"(d[2]), "+f"(d[3])
                 : "r"(a[0]), "r"(a[1]), "r"(a[2]), "r"(a[3]), "r"(b0), "r"(b1));
}
__device__ __forceinline__ void cp16(uint32_t dst, const void* src) {
    asm volatile("cp.async.cg.shared.global [%0], [%1], 16;"
                 :: "r"(dst), "l"(src) : "memory");
}
__device__ __forceinline__ uint32_t hm2(uint32_t v, half2 s) {
    half2 r = __hmul2(*(half2*)&v, s);
    return *(uint32_t*)&r;
}

// dynamic smem layout (bytes)
#define SM_B     0                 // 3 x 16384 : B tiles (triple buffer)
#define SM_STRIP 49152             // 3 x 2048 : per-channel strips
//   per buffer: even @ +0 (512B), odd @ +576 (512B), ivh @ +1088 (256B)
#define SMEM_TOT 55296             // 4 CTAs x 55296 = 221 KB <= 228 KB

// ---------------------------------------------------------------------------
// Main: 128 thr = 4 warps as 2(w) x 2(k); warp tile 64w x 32k; fp16 MMA,
// f32 accumulate across channels. ALL staging is cp.async (strips + iv
// precomputed to fp16 in global), committed one channel ahead. A-fragments
// read from dual even/odd strips, iv folded via hmul2. 1 sync per channel.
// 4 CTAs/SM (16 warps) so prologue/sync beats of one CTA are covered by
// the other three's mainloops.
// ---------------------------------------------------------------------------
__global__ void __launch_bounds__(128, 4) k_main(const float* __restrict__ x,
                                                 float* __restrict__ out) {
    extern __shared__ char dsm[];
    const uint32_t sB0 = (uint32_t)__cvta_generic_to_shared(dsm + SM_B);
    const uint32_t sS0 = (uint32_t)__cvta_generic_to_shared(dsm + SM_STRIP);

    const int tid  = threadIdx.x;
    const int lane = tid & 31, wid = tid >> 5;
    const int ww = wid & 1;            // w direction (64 rows each)
    const int wk = wid >> 1;           // k direction (32 cols each)
    const int w0 = blockIdx.x * WT, k0 = blockIdx.y * KT, b = blockIdx.z;

    // A-fragment strip addressing (per lane)
    const int par = (lane >> 2) & 1;                     // row parity -> e/o strip
    const int qb  = ((ww * 64 + (lane >> 2)) >> 1) + (lane & 3);
    // B ldmatrix lane addressing (2 ldsm.x4 cover 32 k-rows x 16 s)
    const int brow = wk * 32 + ((lane >> 4) & 1) * 8 + (lane & 7);   // + p*16
    const int bhi  = (lane >> 3) & 1;

    float acc[4][4][4];
#pragma unroll
    for (int mi = 0; mi < 4; mi++)
#pragma unroll
        for (int ni = 0; ni < 4; ni++)
#pragma unroll
            for (int d = 0; d < 4; d++) acc[mi][ni][d] = 0.f;

    // ---- all-cp.async staging: strips (1 cp16/thread) + B tile (8/thread) ---
#define STAGE_ALL(ch, bf) do {                                                 \
        int bc = b * C_ + (ch);                                                \
        uint32_t sdst = sS0 + (bf) * 2048;                                     \
        if (tid < 32)                                                          \
            cp16(sdst + tid * 16,                                              \
                 (const char*)g_xe + bc * 8704 + 2 * w0 + tid * 16);           \
        else if (tid < 64)                                                     \
            cp16(sdst + 576 + (tid - 32) * 16,                                 \
                 (const char*)g_xo + bc * 8704 + 2 * w0 + (tid - 32) * 16);    \
        else if (tid < 80)                                                     \
            cp16(sdst + 1088 + (tid - 64) * 16,                                \
                 (const char*)g_invh + bc * 8192 + 2 * w0 + (tid - 64) * 16);  \
        const char* src = (const char*)g_shpB                                  \
                        + (size_t)(blockIdx.y * C_ + (ch)) * 16384;            \
        uint32_t dst = sB0 + (bf) * 16384;                                     \
        _Pragma("unroll")                                                      \
        for (int j = 0; j < 8; j++) {                                          \
            int idx = tid + 128 * j;                                           \
            cp16(dst + idx * 16, src + idx * 16);                              \
        }                                                                      \
        asm volatile("cp.async.commit_group;" ::: "memory");                   \
    } while (0)

    STAGE_ALL(0, 0);

    for (int c = 0; c < C_; c++) {
        const int cb = c % 3;
        if (c + 1 < C_) {
            STAGE_ALL(c + 1, (c + 1) % 3);
            asm volatile("cp.async.wait_group 1;" ::: "memory");
        } else {
            asm volatile("cp.async.wait_group 0;" ::: "memory");
        }
        __syncthreads();   // buffers for c ready; buffers for c+1 in flight

        char* sp = dsm + SM_STRIP + cb * 2048;
        const uint32_t* sv = (const uint32_t*)(sp + (par ? 576 : 0));
        const half* ivh = (const half*)(sp + 1088);

        // per-mi iv broadcasts + rolling strip window init
        half2 ivlo[4], ivhi[4];
        uint32_t vA[4];
#pragma unroll
        for (int mi = 0; mi < 4; mi++) {
            int r0 = ww * 64 + mi * 16 + (lane >> 2);
            ivlo[mi] = __half2half2(ivh[r0]);
            ivhi[mi] = __half2half2(ivh[r0 + 8]);
            vA[mi] = sv[qb + mi * 8];
        }

        const uint32_t sB = sB0 + cb * 16384;
#pragma unroll
        for (int st = 0; st < 8; st++) {
            // A fragments straight from strips: 2 new LDS.32 per mi per step
            uint32_t a[4][4];
#pragma unroll
            for (int mi = 0; mi < 4; mi++) {
                uint32_t vB = sv[qb + mi * 8 + 8 * st + 4];
                uint32_t vC = sv[qb + mi * 8 + 8 * st + 8];
                a[mi][0] = hm2(vA[mi], ivlo[mi]);
                a[mi][1] = hm2(vB,     ivhi[mi]);
                a[mi][2] = hm2(vB,     ivlo[mi]);
                a[mi][3] = hm2(vC,     ivhi[mi]);
                vA[mi] = vC;
            }
            // B fragments: 2 ldmatrix.x4 cover 32 k-rows x 16 s
            uint32_t bb[2][4];
#pragma unroll
            for (int p = 0; p < 2; p++) {
                int row = brow + p * 16;
                uint32_t ad = sB + row * 256 + (((2 * st + bhi) ^ (row & 7)) << 4);
                ldsm4(bb[p], ad);
            }
#pragma unroll
            for (int mi = 0; mi < 4; mi++)
#pragma unroll
                for (int p = 0; p < 2; p++) {
                    mma16816(acc[mi][2 * p + 0], a[mi], bb[p][0], bb[p][1]);
                    mma16816(acc[mi][2 * p + 1], a[mi], bb[p][2], bb[p][3]);
                }
        }
        // no trailing sync: writers at iter c+1 target buffer (c+2)%3,
        // readers here use (c)%3 -- disjoint; one sync per channel suffices.
    }

    // ---- epilogue: relu + max over w (regs + shfl), global atomicMax --------
#pragma unroll
    for (int ni = 0; ni < 4; ni++) {
#pragma unroll
        for (int cc = 0; cc < 2; cc++) {
            float m = 0.f;
#pragma unroll
            for (int mi = 0; mi < 4; mi++)
                m = fmaxf(m, fmaxf(acc[mi][ni][cc], acc[mi][ni][cc + 2]));
            m = fmaxf(m * 0.25f, 0.f);
            m = fmaxf(m, __shfl_xor_sync(0xffffffffu, m, 4));
            m = fmaxf(m, __shfl_xor_sync(0xffffffffu, m, 8));
            m = fmaxf(m, __shfl_xor_sync(0xffffffffu, m, 16));
            if (lane < 4)
                atomicMax((int*)&out[b * K_ + k0 + wk * 32 + ni * 8 + 2 * lane + cc],
                          __float_as_int(m));
        }
    }
}

// ---------------------------------------------------------------------------
extern "C" void kernel_launch(void* const* d_in, const int* in_sizes, int n_in,
                              void* d_out, int out_size) {
    const float* x   = (const float*)d_in[0];   // (16,4,4096)
    const float* shp = (const float*)d_in[1];   // (4,256,128)
    float* out = (float*)d_out;                 // (16,1,256)

    static int attr_done = 0;
    if (!attr_done) {
        cudaFuncSetAttribute(k_main, cudaFuncAttributeMaxDynamicSharedMemorySize,
                             SMEM_TOT);
        attr_done = 1;
    }

    k_prep<<<1536, 256>>>(x, shp, out);
    k_main<<<dim3((W_ + WT - 1) / WT, K_ / KT, B_), 128, SMEM_TOT>>>(x, out);
}

// round 16
// speedup vs baseline: 1.0516x; 1.0516x over previous
#include <cuda_runtime.h>
#include <cuda_fp16.h>
#include <stdint.h>

#define B_ 16
#define C_ 4
#define L_ 4096
#define K_ 256
#define S_ 128
#define W_ (L_ - S_ + 1)   // 3969
#define EPS_ 1e-8f

#define WT 128             // w per block (MMA M)
#define KT 64              // k per block (MMA N)

// Precomputed in prep, consumed via pure cp.async in main:
//  g_xe[bc][j] = (xh[2j], xh[2j+1])   g_xo[bc][j] = (xh[2j+1], xh[2j+2])
//  padded regions stay zero (device globals zero-init, prep never writes
//  them) -> only consumed by iv=0 rows, so they never affect the max.
__device__ __align__(16) uint32_t g_xe[B_ * C_ * 2176];
__device__ __align__(16) uint32_t g_xo[B_ * C_ * 2176];
__device__ __align__(16) __half  g_invh[B_ * C_ * 4096];   // padded W, fp16
// Shapelets normalized -> fp16, PRE-SWIZZLED per-(ktile,channel) 16KB tile
__device__ __align__(256) half g_shpB[C_ * K_ * S_];   // [4 ktiles][4 c][64*128]

// ---------------------------------------------------------------------------
// Merged prep kernel:
//  blocks [0,1024): inverse norms + even/odd half2 strip arrays (+ zero out)
//  blocks [1024,1536): shapelet normalize -> swizzled fp16 image
// ---------------------------------------------------------------------------
__global__ void k_prep(const float* __restrict__ x, const float* __restrict__ shp,
                       float* __restrict__ out) {
    int tid = threadIdx.x;
    if (blockIdx.x < 1024) {
        __shared__ float xs[384];
        int bc = blockIdx.x >> 4;
        int w0 = (blockIdx.x & 15) * 256;
        if (blockIdx.x < 16) out[blockIdx.x * 256 + tid] = 0.f;
        for (int i = tid; i < 383; i += 256) {
            int g = w0 + i;
            xs[i] = (g < L_) ? x[bc * L_ + g] : 0.f;
        }
        __syncthreads();
        int w = w0 + tid;
        if (w < W_) {
            float sum = 0.f;
#pragma unroll 8
            for (int s = 0; s < S_; s++) { float t = xs[tid + s]; sum += t * t; }
            g_invh[bc * 4096 + w] = __float2half(1.f / fmaxf(sqrtf(sum), EPS_));
        }
        if (tid < 128) {
            int j = (w0 >> 1) + tid;
            half2 e = __floats2half2_rn(xs[2 * tid],     xs[2 * tid + 1]);
            half2 o = __floats2half2_rn(xs[2 * tid + 1], xs[2 * tid + 2]);
            g_xe[bc * 2176 + j] = *(uint32_t*)&e;
            g_xo[bc * 2176 + j] = *(uint32_t*)&o;
        }
    } else {
        __shared__ float wsum[8];
        int idx = blockIdx.x - 1024;              // 0..511
        int p = idx * 2 + (tid >> 7);             // (c,k) pair id, 0..1023
        int c = p >> 8, k = p & 255;
        int s = tid & 127;
        float v = shp[(c * K_ + k) * S_ + s];
        float sq = v * v;
#pragma unroll
        for (int o = 16; o > 0; o >>= 1) sq += __shfl_xor_sync(0xffffffffu, sq, o);
        if ((tid & 31) == 0) wsum[tid >> 5] = sq;
        __syncthreads();
        int g4 = (tid >> 7) * 4;
        float tot = wsum[g4] + wsum[g4 + 1] + wsum[g4 + 2] + wsum[g4 + 3];
        float inv = 1.f / fmaxf(sqrtf(tot), EPS_);
        int tile = (k >> 6) * C_ + c;             // 4 ktiles of 64 rows
        int row = k & 63;
        uint32_t off = (uint32_t)row * 256u
                     + ((((uint32_t)(s >> 3)) ^ (row & 7)) << 4)
                     + (uint32_t)(s & 7) * 2u;
        *(half*)((char*)g_shpB + (size_t)tile * 16384 + off) = __float2half(v * inv);
    }
}

// ---------------------------------------------------------------------------
__device__ __forceinline__ void ldsm4(uint32_t (&r)[4], uint32_t addr) {
    asm volatile("ldmatrix.sync.aligned.m8n8.x4.shared.b16 {%0,%1,%2,%3}, [%4];"
                 : "=r"(r[0]), "=r"(r[1]), "=r"(r[2]), "=r"(r[3]) : "r"(addr));
}
__device__ __forceinline__ void mma16816(float (&d)[4], const uint32_t (&a)[4],
                                         uint32_t b0, uint32_t b1) {
    asm volatile("mma.sync.aligned.m16n8k16.row.col.f32.f16.f16.f32 "
                 "{%0,%1,%2,%3}, {%4,%5,%6,%7}, {%8,%9}, {%0,%1,%2,%3};"
                 : "+f"(d[0]), "+f"(d[1]), "+f"(d[2]), "+f"(d[3])
                 : "r"(a[0]), "r"(a[1]), "r"(a[2]), "r"(a[3]), "r"(b0), "r"(b1));
}
__device__ __forceinline__ void cp16(uint32_t dst, const void* src) {
    asm volatile("cp.async.cg.shared.global [%0], [%1], 16;"
                 :: "r"(dst), "l"(src) : "memory");
}
__device__ __forceinline__ uint32_t hm2(uint32_t v, half2 s) {
    half2 r = __hmul2(*(half2*)&v, s);
    return *(uint32_t*)&r;
}

// dynamic smem layout (bytes)
#define SM_B     0                 // 4 x 16384 : B tiles, ALL channels resident
#define SM_STRIP 65536             // 4 x 2048 : per-channel strips, ALL resident
//   per strip buffer: even @ +0 (512B), odd @ +576 (512B), ivh @ +1088 (256B)
#define SMEM_TOT 73728

// ---------------------------------------------------------------------------
// Main: 128 thr = 4 warps as 2(w) x 2(k); warp tile 64w x 32k; fp16 MMA,
// f32 accumulate across channels. ALL cp.async issued in the prologue as
// FOUR commit groups (one per channel); the mainloop waits per channel
// (wait_group 3-c) so HMMA starts after only channel 0's 18 KB lands while
// channels 1-3 stream behind the compute. Zero in-loop staging. 3 CTAs/SM.
// ---------------------------------------------------------------------------
__global__ void __launch_bounds__(128, 3) k_main(const float* __restrict__ x,
                                                 float* __restrict__ out) {
    extern __shared__ char dsm[];
    const uint32_t sB0 = (uint32_t)__cvta_generic_to_shared(dsm + SM_B);
    const uint32_t sS0 = (uint32_t)__cvta_generic_to_shared(dsm + SM_STRIP);

    const int tid  = threadIdx.x;
    const int lane = tid & 31, wid = tid >> 5;
    const int ww = wid & 1;            // w direction (64 rows each)
    const int wk = wid >> 1;           // k direction (32 cols each)
    const int w0 = blockIdx.x * WT, k0 = blockIdx.y * KT, b = blockIdx.z;

    // A-fragment strip addressing (per lane)
    const int par = (lane >> 2) & 1;                     // row parity -> e/o strip
    const int qb  = ((ww * 64 + (lane >> 2)) >> 1) + (lane & 3);
    // B ldmatrix lane addressing (2 ldsm.x4 cover 32 k-rows x 16 s)
    const int brow = wk * 32 + ((lane >> 4) & 1) * 8 + (lane & 7);   // + p*16
    const int bhi  = (lane >> 3) & 1;

    float acc[4][4][4];
#pragma unroll
    for (int mi = 0; mi < 4; mi++)
#pragma unroll
        for (int ni = 0; ni < 4; ni++)
#pragma unroll
            for (int d = 0; d < 4; d++) acc[mi][ni][d] = 0.f;

    // ---- prologue: issue ALL staging, one commit group per channel ---------
#pragma unroll
    for (int ch = 0; ch < C_; ch++) {
        int bc = b * C_ + ch;
        uint32_t sdst = sS0 + ch * 2048;
        if (tid < 32)
            cp16(sdst + tid * 16,
                 (const char*)g_xe + bc * 8704 + 2 * w0 + tid * 16);
        else if (tid < 64)
            cp16(sdst + 576 + (tid - 32) * 16,
                 (const char*)g_xo + bc * 8704 + 2 * w0 + (tid - 32) * 16);
        else if (tid < 80)
            cp16(sdst + 1088 + (tid - 64) * 16,
                 (const char*)g_invh + bc * 8192 + 2 * w0 + (tid - 64) * 16);
        const char* src = (const char*)g_shpB
                        + (size_t)(blockIdx.y * C_ + ch) * 16384;
        uint32_t dst = sB0 + ch * 16384;
#pragma unroll
        for (int j = 0; j < 8; j++) {
            int idx = tid + 128 * j;
            cp16(dst + idx * 16, src + idx * 16);
        }
        asm volatile("cp.async.commit_group;" ::: "memory");
    }

#pragma unroll
    for (int c = 0; c < C_; c++) {
        // groups 0..c must have completed -> at most (3-c) still pending
        if (c == 0)      asm volatile("cp.async.wait_group 3;" ::: "memory");
        else if (c == 1) asm volatile("cp.async.wait_group 2;" ::: "memory");
        else if (c == 2) asm volatile("cp.async.wait_group 1;" ::: "memory");
        else             asm volatile("cp.async.wait_group 0;" ::: "memory");
        __syncthreads();   // channel-c buffers visible CTA-wide

        char* sp = dsm + SM_STRIP + c * 2048;
        const uint32_t* sv = (const uint32_t*)(sp + (par ? 576 : 0));
        const half* ivh = (const half*)(sp + 1088);

        // per-mi iv broadcasts + rolling strip window init
        half2 ivlo[4], ivhi[4];
        uint32_t vA[4];
#pragma unroll
        for (int mi = 0; mi < 4; mi++) {
            int r0 = ww * 64 + mi * 16 + (lane >> 2);
            ivlo[mi] = __half2half2(ivh[r0]);
            ivhi[mi] = __half2half2(ivh[r0 + 8]);
            vA[mi] = sv[qb + mi * 8];
        }

        const uint32_t sB = sB0 + c * 16384;
#pragma unroll
        for (int st = 0; st < 8; st++) {
            // A fragments straight from strips: 2 new LDS.32 per mi per step
            uint32_t a[4][4];
#pragma unroll
            for (int mi = 0; mi < 4; mi++) {
                uint32_t vB = sv[qb + mi * 8 + 8 * st + 4];
                uint32_t vC = sv[qb + mi * 8 + 8 * st + 8];
                a[mi][0] = hm2(vA[mi], ivlo[mi]);
                a[mi][1] = hm2(vB,     ivhi[mi]);
                a[mi][2] = hm2(vB,     ivlo[mi]);
                a[mi][3] = hm2(vC,     ivhi[mi]);
                vA[mi] = vC;
            }
            // B fragments: 2 ldmatrix.x4 cover 32 k-rows x 16 s
            uint32_t bb[2][4];
#pragma unroll
            for (int p = 0; p < 2; p++) {
                int row = brow + p * 16;
                uint32_t ad = sB + row * 256 + (((2 * st + bhi) ^ (row & 7)) << 4);
                ldsm4(bb[p], ad);
            }
#pragma unroll
            for (int mi = 0; mi < 4; mi++)
#pragma unroll
                for (int p = 0; p < 2; p++) {
                    mma16816(acc[mi][2 * p + 0], a[mi], bb[p][0], bb[p][1]);
                    mma16816(acc[mi][2 * p + 1], a[mi], bb[p][2], bb[p][3]);
                }
        }
    }

    // ---- epilogue: relu + max over w (regs + shfl), global atomicMax --------
#pragma unroll
    for (int ni = 0; ni < 4; ni++) {
#pragma unroll
        for (int cc = 0; cc < 2; cc++) {
            float m = 0.f;
#pragma unroll
            for (int mi = 0; mi < 4; mi++)
                m = fmaxf(m, fmaxf(acc[mi][ni][cc], acc[mi][ni][cc + 2]));
            m = fmaxf(m * 0.25f, 0.f);
            m = fmaxf(m, __shfl_xor_sync(0xffffffffu, m, 4));
            m = fmaxf(m, __shfl_xor_sync(0xffffffffu, m, 8));
            m = fmaxf(m, __shfl_xor_sync(0xffffffffu, m, 16));
            if (lane < 4)
                atomicMax((int*)&out[b * K_ + k0 + wk * 32 + ni * 8 + 2 * lane + cc],
                          __float_as_int(m));
        }
    }
}

// ---------------------------------------------------------------------------
extern "C" void kernel_launch(void* const* d_in, const int* in_sizes, int n_in,
                              void* d_out, int out_size) {
    const float* x   = (const float*)d_in[0];   // (16,4,4096)
    const float* shp = (const float*)d_in[1];   // (4,256,128)
    float* out = (float*)d_out;                 // (16,1,256)

    static int attr_done = 0;
    if (!attr_done) {
        cudaFuncSetAttribute(k_main, cudaFuncAttributeMaxDynamicSharedMemorySize,
                             SMEM_TOT);
        attr_done = 1;
    }

    k_prep<<<1536, 256>>>(x, shp, out);
    k_main<<<dim3((W_ + WT - 1) / WT, K_ / KT, B_), 128, SMEM_TOT>>>(x, out);
}